// round 10
// baseline (speedup 1.0000x reference)
#include <cuda_runtime.h>
#include <cuda_fp16.h>
#include <cstdint>

// KMeans labels via legacy fp16 tensor cores (mma.sync m16n8k16).
// score(i,k) = ||c_k||^2 - 2<x_i,c_k>.  fp32 = h + l fp16 split (natural l),
// terms hh+hl+lh.  768-thread CTA (24 warps = 6/SMSP for latency hiding),
// TILE_M=192, warp tile M32xN32 (acc 32 regs), all B resident in smem.

#define DIM      64
#define KCENT    512
#define TILE_M   192
#define CHN      128
#define NCH      4
#define THREADS  768

// smem byte offsets (XOR-swizzled 128B rows)
#define SA    0u          // 2 vars * 192 rows * 128B = 49152
#define SB    49152u      // 4 ch * 2 vars * 128 rows * 128B = 131072
#define SC2   180224u     // 512 f32 = 2048
#define SRV   182272u     // 4*192 f32 = 3072
#define SRI   185344u     // 4*192 i32 = 3072
#define SMEM_BYTES 188416u

__device__ __align__(16) __half g_bh[KCENT][DIM];   // rn16(-2c)
__device__ __align__(16) __half g_bl[KCENT][DIM];   // rn16(-2c - h)
__device__ __align__(16) float  g_c2[KCENT];

__device__ __forceinline__ uint32_t smem_u32(const void* p) {
    uint32_t a;
    asm("{ .reg .u64 t; cvta.to.shared.u64 t, %1; cvt.u32.u64 %0, t; }"
        : "=r"(a) : "l"(p));
    return a;
}

__device__ __forceinline__ uint32_t pack_h2(__half a, __half b) {
    __half2 t = __halves2half2(a, b);
    return *reinterpret_cast<uint32_t*>(&t);
}

__device__ __forceinline__ void ldm_x4(uint32_t* r, uint32_t addr) {
    asm volatile("ldmatrix.sync.aligned.m8n8.x4.shared.b16 {%0,%1,%2,%3}, [%4];"
                 : "=r"(r[0]), "=r"(r[1]), "=r"(r[2]), "=r"(r[3]) : "r"(addr));
}

__device__ __forceinline__ void mma_f16(float* c, const uint32_t* a,
                                        const uint32_t* b) {
    asm volatile(
        "mma.sync.aligned.m16n8k16.row.col.f32.f16.f16.f32 "
        "{%0,%1,%2,%3}, {%4,%5,%6,%7}, {%8,%9}, {%0,%1,%2,%3};"
        : "+f"(c[0]), "+f"(c[1]), "+f"(c[2]), "+f"(c[3])
        : "r"(a[0]), "r"(a[1]), "r"(a[2]), "r"(a[3]), "r"(b[0]), "r"(b[1]));
}

template <int N>
__device__ __forceinline__ void cp_wait() {
    asm volatile("cp.async.wait_group %0;" :: "n"(N));
}

// (va,ia) vs (vb,ib) with ia < ib: strict < keeps first occurrence.
__device__ __forceinline__ void tmin(float& va, int& ia, float vb, int ib) {
    if (vb < va) { va = vb; ia = ib; }
}

// ---------------- prep: fp16 split of -2*centroids + ||c||^2 ----------------
__global__ void prep_kernel(const float* __restrict__ cent)
{
    int r = blockIdx.x * blockDim.x + threadIdx.x;
    if (r >= KCENT) return;
    float s = 0.f;
#pragma unroll
    for (int d = 0; d < DIM; d++) {
        float c = cent[r * DIM + d];
        s = fmaf(c, c, s);
        float v = -2.f * c;                        // exact
        __half h = __float2half_rn(v);
        g_bh[r][d] = h;
        g_bl[r][d] = __float2half_rn(v - __half2float(h));
    }
    g_c2[r] = s;
}

// ---------------- main kernel ----------------
extern __shared__ char smc[];

__global__ __launch_bounds__(THREADS, 1)
void kmeans_mma_kernel(const float* __restrict__ x,
                       float* __restrict__ out, int n)
{
    const int tid = threadIdx.x;
    const int lid = tid & 31;
    const int wid = tid >> 5;
    const int wm  = wid >> 2;     // 0..5  M groups of 32
    const int wn  = wid & 3;      // 0..3  N quarters of 32
    const int lr  = lid >> 2;     // 0..7
    const int lc  = lid & 3;      // 0..3

    const uint32_t smb = smem_u32(smc);

    // ---- issue B chunk loads: 4 commit groups ----
#pragma unroll
    for (int ch = 0; ch < NCH; ch++) {
        for (int it = tid; it < 2048; it += THREADS) {
            int var = it >> 10;
            int rem = it & 1023;
            int r   = rem >> 3;
            int q   = rem & 7;
            const __half* src = var ? &g_bl[ch * CHN + r][q * 8]
                                    : &g_bh[ch * CHN + r][q * 8];
            uint64_t gs;
            asm("cvta.to.global.u64 %0, %1;" : "=l"(gs) : "l"(src));
            uint32_t ds = smb + SB + (uint32_t)ch * 32768u +
                          (uint32_t)var * 16384u + (uint32_t)r * 128u +
                          (uint32_t)((q ^ (r & 7)) << 4);
            asm volatile("cp.async.cg.shared.global [%0], [%1], 16;"
                         :: "r"(ds), "l"(gs));
        }
        asm volatile("cp.async.commit_group;");
    }

    // ---- stage c2 (512 floats) ----
    if (tid < KCENT)
        reinterpret_cast<float*>(smc + SC2)[tid] = g_c2[tid];

    // ---- stage A (fp16 split, swizzled): row = tid/2, half = tid&1 ----
    if (tid < 2 * TILE_M) {
        const int  r2 = tid >> 1, hf = tid & 1;
        const int  grow = blockIdx.x * TILE_M + r2;
        const bool vld = (grow < n);
        const float4* xr =
            reinterpret_cast<const float4*>(x + (size_t)grow * DIM) + hf * 8;
        const float4 z = make_float4(0.f, 0.f, 0.f, 0.f);
        const int rs = r2 & 7;
#pragma unroll
        for (int j = 0; j < 8; j++) {
            float4 c = vld ? xr[j] : z;
            float a[4] = {c.x, c.y, c.z, c.w};
            __half h[4], l[4];
#pragma unroll
            for (int q = 0; q < 4; q++) {
                h[q] = __float2half_rn(a[q]);
                l[q] = __float2half_rn(a[q] - __half2float(h[q]));
            }
            const int colb = hf * 64 + j * 8;
            const int qidx = colb >> 4;
            const uint32_t off =
                (uint32_t)r2 * 128u + (uint32_t)((qidx ^ rs) << 4) +
                (uint32_t)(colb & 15);
            *reinterpret_cast<uint2*>(smc + SA + off) =
                make_uint2(pack_h2(h[0], h[1]), pack_h2(h[2], h[3]));
            *reinterpret_cast<uint2*>(smc + SA + 24576u + off) =
                make_uint2(pack_h2(l[0], l[1]), pack_h2(l[2], l[3]));
        }
    }

    // A lane addressing (ldmatrix x4: m16 x k16)
    const int arow = ((lid >> 3) & 1) * 8 + (lid & 7);
    const int aq0  = lid >> 4;
    const int asw  = lid & 7;
    uint32_t a_base[2][2];
#pragma unroll
    for (int v = 0; v < 2; v++)
#pragma unroll
        for (int mt = 0; mt < 2; mt++)
            a_base[v][mt] = smb + SA + (uint32_t)v * 24576u +
                            (uint32_t)(wm * 32 + mt * 16 + arow) * 128u;

    // B lane addressing (ldmatrix x4: two n8k16 fragments per load)
    const int brow = ((lid >> 4) & 1) * 8 + (lid & 7);
    const int bq0  = (lid >> 3) & 1;
    const int bsw  = lid & 7;
    const uint32_t b_row_off = (uint32_t)(wn * 32 + brow) * 128u;

    float bv[2][2] = {{3.4e38f, 3.4e38f}, {3.4e38f, 3.4e38f}};
    int   bi[2][2] = {{0, 0}, {0, 0}};

    auto compute = [&](int ch) {
        float acc[2][4][4];
        const float* c2s =
            reinterpret_cast<const float*>(smc + SC2) + ch * CHN + wn * 32 + 2 * lc;
#pragma unroll
        for (int nt = 0; nt < 4; nt++) {
            float2 cc = *reinterpret_cast<const float2*>(c2s + nt * 8);
#pragma unroll
            for (int mt = 0; mt < 2; mt++) {
                acc[mt][nt][0] = cc.x; acc[mt][nt][1] = cc.y;
                acc[mt][nt][2] = cc.x; acc[mt][nt][3] = cc.y;
            }
        }

        const uint32_t bb0 = smb + SB + (uint32_t)ch * 32768u + b_row_off;
        const uint32_t bb1 = bb0 + 16384u;
        const int idx0 = ch * CHN + wn * 32 + 2 * lc;

#pragma unroll
        for (int s = 0; s < 4; s++) {
            uint32_t ah[2][4], al[2][4];
            const uint32_t aoff = (uint32_t)(((2 * s + aq0) ^ asw) << 4);
#pragma unroll
            for (int mt = 0; mt < 2; mt++) {
                ldm_x4(ah[mt], a_base[0][mt] + aoff);
                ldm_x4(al[mt], a_base[1][mt] + aoff);
            }
            const uint32_t boff = (uint32_t)(((2 * s + bq0) ^ bsw) << 4);
#pragma unroll
            for (int p = 0; p < 2; p++) {
                uint32_t bh4[4], bl4[4];
                const uint32_t ro = (uint32_t)(p * 16) * 128u + boff;
                ldm_x4(bh4, bb0 + ro);
                ldm_x4(bl4, bb1 + ro);
                float* a0 = acc[0][2 * p]; float* a1 = acc[0][2 * p + 1];
                float* a2 = acc[1][2 * p]; float* a3 = acc[1][2 * p + 1];
                // grouped hh -> hl -> lh: dependent MMAs 4 slots apart
                mma_f16(a0, ah[0], bh4);
                mma_f16(a1, ah[0], bh4 + 2);
                mma_f16(a2, ah[1], bh4);
                mma_f16(a3, ah[1], bh4 + 2);
                mma_f16(a0, ah[0], bl4);
                mma_f16(a1, ah[0], bl4 + 2);
                mma_f16(a2, ah[1], bl4);
                mma_f16(a3, ah[1], bl4 + 2);
                mma_f16(a0, al[0], bh4);
                mma_f16(a1, al[0], bh4 + 2);
                mma_f16(a2, al[1], bh4);
                mma_f16(a3, al[1], bh4 + 2);
            }
        }

        // ---- tournament argmin over this chunk ----
#pragma unroll
        for (int mt = 0; mt < 2; mt++) {
#pragma unroll
            for (int hc = 0; hc < 2; hc++) {
                float v[4]; int ix[4];
#pragma unroll
                for (int nt = 0; nt < 4; nt++) {
                    float v0 = acc[mt][nt][2 * hc];
                    float v1 = acc[mt][nt][2 * hc + 1];
                    int   i0 = idx0 + nt * 8;
                    v[nt] = v0; ix[nt] = i0;
                    tmin(v[nt], ix[nt], v1, i0 + 1);
                }
                tmin(v[0], ix[0], v[1], ix[1]);
                tmin(v[2], ix[2], v[3], ix[3]);
                tmin(v[0], ix[0], v[2], ix[2]);
                tmin(bv[mt][hc], bi[mt][hc], v[0], ix[0]);
            }
        }
    };

    // ---- pipeline: one wait + one barrier per chunk ----
    cp_wait<3>(); __syncthreads();
    compute(0);
    cp_wait<2>(); __syncthreads();
    compute(1);
    cp_wait<1>(); __syncthreads();
    compute(2);
    cp_wait<0>(); __syncthreads();
    compute(3);

    // reduce over the 4-lane column groups (lexicographic: first occurrence)
#pragma unroll
    for (int mt = 0; mt < 2; mt++) {
#pragma unroll
        for (int h = 0; h < 2; h++) {
#pragma unroll
            for (int d = 1; d <= 2; d <<= 1) {
                float ov = __shfl_xor_sync(0xFFFFFFFFu, bv[mt][h], d);
                int   oi = __shfl_xor_sync(0xFFFFFFFFu, bi[mt][h], d);
                if (ov < bv[mt][h] || (ov == bv[mt][h] && oi < bi[mt][h])) {
                    bv[mt][h] = ov; bi[mt][h] = oi;
                }
            }
        }
    }
    if (lc == 0) {
#pragma unroll
        for (int mt = 0; mt < 2; mt++) {
#pragma unroll
            for (int h = 0; h < 2; h++) {
                int rowl = wm * 32 + mt * 16 + h * 8 + lr;
                reinterpret_cast<float*>(smc + SRV)[wn * TILE_M + rowl] = bv[mt][h];
                reinterpret_cast<int*>(smc + SRI)[wn * TILE_M + rowl]   = bi[mt][h];
            }
        }
    }
    __syncthreads();

    if (tid < TILE_M) {
        const float* rv = reinterpret_cast<const float*>(smc + SRV);
        const int*   ri = reinterpret_cast<const int*>(smc + SRI);
        float bestv = rv[tid];
        int   besti = ri[tid];
#pragma unroll
        for (int g = 1; g < 4; g++) {
            float v = rv[g * TILE_M + tid];
            int   i = ri[g * TILE_M + tid];
            if (v < bestv || (v == bestv && i < besti)) { bestv = v; besti = i; }
        }
        int grow = blockIdx.x * TILE_M + tid;
        if (grow < n) out[grow] = (float)besti;
    }
}

// ---------------- launch ----------------
extern "C" void kernel_launch(void* const* d_in, const int* in_sizes, int n_in,
                              void* d_out, int out_size)
{
    const float* x = (const float*)d_in[0];     // [N, 64] fp32
    const float* c = (const float*)d_in[1];     // [512, 64] fp32
    float* out = (float*)d_out;                 // [N] labels as float

    const int n = in_sizes[0] / DIM;

    cudaFuncSetAttribute(kmeans_mma_kernel,
                         cudaFuncAttributeMaxDynamicSharedMemorySize,
                         SMEM_BYTES);

    prep_kernel<<<4, 128>>>(c);
    const int grid = (n + TILE_M - 1) / TILE_M;
    kmeans_mma_kernel<<<grid, THREADS, SMEM_BYTES>>>(x, out, n);
}

// round 11
// speedup vs baseline: 1.0935x; 1.0935x over previous
#include <cuda_runtime.h>
#include <cuda_fp16.h>
#include <cstdint>

// KMeans labels via legacy fp16 tensor cores (mma.sync m16n8k16).
// score(i,k) = ||c_k||^2 - 2<x_i,c_k>.  fp32 = h + l fp16 split (natural l),
// terms hh+hl+lh.  512-thread CTA, TILE_M=256, warp tile M32xN64, all B
// resident in smem.  A fragments loaded ONCE into registers and reused for
// all 4 chunks (LDSM -25%); accumulators live per nt-pair only (16 regs).

#define DIM      64
#define KCENT    512
#define TILE_M   256
#define CHN      128
#define NCH      4
#define THREADS  512

// smem byte offsets (XOR-swizzled 128B rows)
#define SA    0u          // 2 vars * 256 rows * 128B = 65536
#define SB    65536u      // 4 ch * 2 vars * 128 rows * 128B = 131072
#define SC2   196608u     // 512 f32
#define SRV   198656u     // 2*256 f32
#define SRI   200704u     // 2*256 i32
#define SMEM_BYTES 202752u

__device__ __align__(16) __half g_bh[KCENT][DIM];   // rn16(-2c)
__device__ __align__(16) __half g_bl[KCENT][DIM];   // rn16(-2c - h)
__device__ __align__(16) float  g_c2[KCENT];

__device__ __forceinline__ uint32_t smem_u32(const void* p) {
    uint32_t a;
    asm("{ .reg .u64 t; cvta.to.shared.u64 t, %1; cvt.u32.u64 %0, t; }"
        : "=r"(a) : "l"(p));
    return a;
}

__device__ __forceinline__ uint32_t pack_h2(__half a, __half b) {
    __half2 t = __halves2half2(a, b);
    return *reinterpret_cast<uint32_t*>(&t);
}

__device__ __forceinline__ void ldm_x4(uint32_t* r, uint32_t addr) {
    asm volatile("ldmatrix.sync.aligned.m8n8.x4.shared.b16 {%0,%1,%2,%3}, [%4];"
                 : "=r"(r[0]), "=r"(r[1]), "=r"(r[2]), "=r"(r[3]) : "r"(addr));
}

__device__ __forceinline__ void mma_f16(float* c, const uint32_t* a,
                                        const uint32_t* b) {
    asm volatile(
        "mma.sync.aligned.m16n8k16.row.col.f32.f16.f16.f32 "
        "{%0,%1,%2,%3}, {%4,%5,%6,%7}, {%8,%9}, {%0,%1,%2,%3};"
        : "+f"(c[0]), "+f"(c[1]), "+f"(c[2]), "+f"(c[3])
        : "r"(a[0]), "r"(a[1]), "r"(a[2]), "r"(a[3]), "r"(b[0]), "r"(b[1]));
}

template <int N>
__device__ __forceinline__ void cp_wait() {
    asm volatile("cp.async.wait_group %0;" :: "n"(N));
}

// (va,ia) vs (vb,ib) with ia < ib: strict < keeps first occurrence.
__device__ __forceinline__ void tmin(float& va, int& ia, float vb, int ib) {
    if (vb < va) { va = vb; ia = ib; }
}

// ---------------- prep: fp16 split of -2*centroids + ||c||^2 ----------------
__global__ void prep_kernel(const float* __restrict__ cent)
{
    int r = blockIdx.x * blockDim.x + threadIdx.x;
    if (r >= KCENT) return;
    float s = 0.f;
#pragma unroll
    for (int d = 0; d < DIM; d++) {
        float c = cent[r * DIM + d];
        s = fmaf(c, c, s);
        float v = -2.f * c;                        // exact
        __half h = __float2half_rn(v);
        g_bh[r][d] = h;
        g_bl[r][d] = __float2half_rn(v - __half2float(h));
    }
    g_c2[r] = s;
}

// ---------------- main kernel ----------------
extern __shared__ char smc[];

__global__ __launch_bounds__(THREADS, 1)
void kmeans_mma_kernel(const float* __restrict__ x,
                       float* __restrict__ out, int n)
{
    const int tid = threadIdx.x;
    const int lid = tid & 31;
    const int wid = tid >> 5;
    const int wm  = wid >> 1;     // 0..7  M groups of 32
    const int wn  = wid & 1;      // 0..1  N halves of 64
    const int lr  = lid >> 2;     // 0..7
    const int lc  = lid & 3;      // 0..3

    const uint32_t smb = smem_u32(smc);

    // ---- issue B chunk loads: 4 commit groups ----
#pragma unroll
    for (int ch = 0; ch < NCH; ch++) {
#pragma unroll
        for (int j = 0; j < 4; j++) {
            int it  = tid + j * THREADS;           // 0..2047
            int var = it >> 10;
            int rem = it & 1023;
            int r   = rem >> 3;
            int q   = rem & 7;
            const __half* src = var ? &g_bl[ch * CHN + r][q * 8]
                                    : &g_bh[ch * CHN + r][q * 8];
            uint64_t gs;
            asm("cvta.to.global.u64 %0, %1;" : "=l"(gs) : "l"(src));
            uint32_t ds = smb + SB + (uint32_t)ch * 32768u +
                          (uint32_t)var * 16384u + (uint32_t)r * 128u +
                          (uint32_t)((q ^ (r & 7)) << 4);
            asm volatile("cp.async.cg.shared.global [%0], [%1], 16;"
                         :: "r"(ds), "l"(gs));
        }
        asm volatile("cp.async.commit_group;");
    }

    // ---- stage c2 (512 floats) ----
    reinterpret_cast<float*>(smc + SC2)[tid] = g_c2[tid];

    // ---- stage A (fp16 split, swizzled): row = tid/2, half = tid&1 ----
    {
        const int  r2 = tid >> 1, hf = tid & 1;
        const int  grow = blockIdx.x * TILE_M + r2;
        const bool vld = (grow < n);
        const float4* xr =
            reinterpret_cast<const float4*>(x + (size_t)grow * DIM) + hf * 8;
        const float4 z = make_float4(0.f, 0.f, 0.f, 0.f);
        const int rs = r2 & 7;
#pragma unroll
        for (int j = 0; j < 8; j++) {
            float4 c = vld ? xr[j] : z;
            float a[4] = {c.x, c.y, c.z, c.w};
            __half h[4], l[4];
#pragma unroll
            for (int q = 0; q < 4; q++) {
                h[q] = __float2half_rn(a[q]);
                l[q] = __float2half_rn(a[q] - __half2float(h[q]));
            }
            const int colb = hf * 64 + j * 8;
            const int qidx = colb >> 4;
            const uint32_t off =
                (uint32_t)r2 * 128u + (uint32_t)((qidx ^ rs) << 4) +
                (uint32_t)(colb & 15);
            *reinterpret_cast<uint2*>(smc + SA + off) =
                make_uint2(pack_h2(h[0], h[1]), pack_h2(h[2], h[3]));
            *reinterpret_cast<uint2*>(smc + SA + 32768u + off) =
                make_uint2(pack_h2(l[0], l[1]), pack_h2(l[2], l[3]));
        }
    }

    // A lane addressing (ldmatrix x4: m16 x k16)
    const int arow = ((lid >> 3) & 1) * 8 + (lid & 7);
    const int aq0  = lid >> 4;
    const int asw  = lid & 7;

    // B lane addressing (ldmatrix x4: two n8k16 fragments per load)
    const int brow = ((lid >> 4) & 1) * 8 + (lid & 7);
    const int bq0  = (lid >> 3) & 1;
    const int bsw  = lid & 7;
    const uint32_t b_row_off = (uint32_t)(wn * 64 + brow) * 128u;

    float bv[2][2] = {{3.4e38f, 3.4e38f}, {3.4e38f, 3.4e38f}};
    int   bi[2][2] = {{0, 0}, {0, 0}};

    // ---- wait for chunk 0 + A/c2 staged, then load ALL A fragments ONCE ----
    cp_wait<3>(); __syncthreads();

    uint32_t AH[4][2][4], AL[4][2][4];    // [s][mt][frag] — 64 regs, persistent
#pragma unroll
    for (int s = 0; s < 4; s++) {
        const uint32_t aoff = (uint32_t)(((2 * s + aq0) ^ asw) << 4);
#pragma unroll
        for (int mt = 0; mt < 2; mt++) {
            const uint32_t rowb =
                (uint32_t)(wm * 32 + mt * 16 + arow) * 128u;
            ldm_x4(AH[s][mt], smb + SA + rowb + aoff);
            ldm_x4(AL[s][mt], smb + SA + 32768u + rowb + aoff);
        }
    }

    auto compute = [&](int ch) {
        const uint32_t bb0 = smb + SB + (uint32_t)ch * 32768u + b_row_off;
        const uint32_t bb1 = bb0 + 16384u;
        const int idx0 = ch * CHN + wn * 64 + 2 * lc;
        const float* c2s =
            reinterpret_cast<const float*>(smc + SC2) + ch * CHN + wn * 64 + 2 * lc;

#pragma unroll
        for (int p = 0; p < 4; p++) {
            // accumulators for nt = 2p, 2p+1 only (16 regs)
            float acc[2][2][4];
            {
                float2 cc0 = *reinterpret_cast<const float2*>(c2s + (2 * p) * 8);
                float2 cc1 = *reinterpret_cast<const float2*>(c2s + (2 * p + 1) * 8);
#pragma unroll
                for (int mt = 0; mt < 2; mt++) {
                    acc[mt][0][0] = cc0.x; acc[mt][0][1] = cc0.y;
                    acc[mt][0][2] = cc0.x; acc[mt][0][3] = cc0.y;
                    acc[mt][1][0] = cc1.x; acc[mt][1][1] = cc1.y;
                    acc[mt][1][2] = cc1.x; acc[mt][1][3] = cc1.y;
                }
            }

#pragma unroll
            for (int s = 0; s < 4; s++) {
                uint32_t bh4[4], bl4[4];
                const uint32_t ro = (uint32_t)(p * 16) * 128u +
                                    (uint32_t)(((2 * s + bq0) ^ bsw) << 4);
                ldm_x4(bh4, bb0 + ro);
                ldm_x4(bl4, bb1 + ro);
                // grouped hh -> hl -> lh: dependent MMAs 4 slots apart
                mma_f16(acc[0][0], AH[s][0], bh4);
                mma_f16(acc[0][1], AH[s][0], bh4 + 2);
                mma_f16(acc[1][0], AH[s][1], bh4);
                mma_f16(acc[1][1], AH[s][1], bh4 + 2);
                mma_f16(acc[0][0], AH[s][0], bl4);
                mma_f16(acc[0][1], AH[s][0], bl4 + 2);
                mma_f16(acc[1][0], AH[s][1], bl4);
                mma_f16(acc[1][1], AH[s][1], bl4 + 2);
                mma_f16(acc[0][0], AL[s][0], bh4);
                mma_f16(acc[0][1], AL[s][0], bh4 + 2);
                mma_f16(acc[1][0], AL[s][1], bh4);
                mma_f16(acc[1][1], AL[s][1], bh4 + 2);
            }

            // fold argmin for nt = 2p, 2p+1 (tournament, first occurrence)
#pragma unroll
            for (int mt = 0; mt < 2; mt++) {
#pragma unroll
                for (int hc = 0; hc < 2; hc++) {
                    float v0 = acc[mt][0][2 * hc];
                    int   i0 = idx0 + (2 * p) * 8;
                    tmin(v0, i0, acc[mt][0][2 * hc + 1], i0 + 1);
                    float v1 = acc[mt][1][2 * hc];
                    int   i1 = idx0 + (2 * p + 1) * 8;
                    tmin(v1, i1, acc[mt][1][2 * hc + 1], i1 + 1);
                    tmin(v0, i0, v1, i1);
                    tmin(bv[mt][hc], bi[mt][hc], v0, i0);
                }
            }
        }
    };

    compute(0);
    cp_wait<2>(); __syncthreads();
    compute(1);
    cp_wait<1>(); __syncthreads();
    compute(2);
    cp_wait<0>(); __syncthreads();
    compute(3);

    // reduce over the 4-lane column groups (lexicographic: first occurrence)
#pragma unroll
    for (int mt = 0; mt < 2; mt++) {
#pragma unroll
        for (int h = 0; h < 2; h++) {
#pragma unroll
            for (int d = 1; d <= 2; d <<= 1) {
                float ov = __shfl_xor_sync(0xFFFFFFFFu, bv[mt][h], d);
                int   oi = __shfl_xor_sync(0xFFFFFFFFu, bi[mt][h], d);
                if (ov < bv[mt][h] || (ov == bv[mt][h] && oi < bi[mt][h])) {
                    bv[mt][h] = ov; bi[mt][h] = oi;
                }
            }
        }
    }
    if (lc == 0) {
#pragma unroll
        for (int mt = 0; mt < 2; mt++) {
#pragma unroll
            for (int h = 0; h < 2; h++) {
                int rowl = wm * 32 + mt * 16 + h * 8 + lr;
                reinterpret_cast<float*>(smc + SRV)[wn * 256 + rowl] = bv[mt][h];
                reinterpret_cast<int*>(smc + SRI)[wn * 256 + rowl]   = bi[mt][h];
            }
        }
    }
    __syncthreads();

    if (tid < TILE_M) {
        float v0 = reinterpret_cast<float*>(smc + SRV)[tid];
        float v1 = reinterpret_cast<float*>(smc + SRV)[256 + tid];
        int   i0 = reinterpret_cast<int*>(smc + SRI)[tid];
        int   i1 = reinterpret_cast<int*>(smc + SRI)[256 + tid];
        int best = (v1 < v0 || (v1 == v0 && i1 < i0)) ? i1 : i0;
        int grow = blockIdx.x * TILE_M + tid;
        if (grow < n) out[grow] = (float)best;
    }
}

// ---------------- launch ----------------
extern "C" void kernel_launch(void* const* d_in, const int* in_sizes, int n_in,
                              void* d_out, int out_size)
{
    const float* x = (const float*)d_in[0];     // [N, 64] fp32
    const float* c = (const float*)d_in[1];     // [512, 64] fp32
    float* out = (float*)d_out;                 // [N] labels as float

    const int n = in_sizes[0] / DIM;

    cudaFuncSetAttribute(kmeans_mma_kernel,
                         cudaFuncAttributeMaxDynamicSharedMemorySize,
                         SMEM_BYTES);

    prep_kernel<<<4, 128>>>(c);
    const int grid = (n + TILE_M - 1) / TILE_M;
    kmeans_mma_kernel<<<grid, THREADS, SMEM_BYTES>>>(x, out, n);
}